// round 7
// baseline (speedup 1.0000x reference)
#include <cuda_runtime.h>
#include <cuda_bf16.h>
#include <math.h>

// Problem constants
#define B 64
#define NA 33600            // 160*160 + 80*80 + 40*40
#define NA4 8400            // NA / 4
#define TOPK 500
#define CAND 1024           // candidate sort size
#define NBIN 1024           // linear histogram bins over (0.3, 1.0]
#define SCORE_THRESH 0.3f
#define NMS_THRESH 0.5f
#define CLASS_OFFSET 10000.0f

#define P3_END 25600
#define P4_END 32000

typedef unsigned long long ull;

// ---------------- scratch (static device allocations; no runtime alloc) ----
__device__ float g_scores[B * NA];      // written ONLY by the exact fallback path
__device__ ull   g_cand[B * NA];        // per-batch approx candidate keys
__device__ int   g_cnt[B];              // per-batch candidate counts
__device__ int   g_hist[B][NBIN];       // per-batch approx-score histograms

// ------------------------------------------------------------ exp/sigmoid --
// Correctly-rounded float exp via double exp (matches XLA:CPU expf).
// Verified bit-compatible in R4/R5/R6 — DO NOT change.
__device__ __forceinline__ float exp_cr(float x) {
    return (float)exp((double)x);
}
__device__ __forceinline__ float sig_e(float x) {
    float e = exp_cr(-x);
    return __fdiv_rn(1.0f, __fadd_rn(1.0f, e));
}
// fast sigmoid for the approximate path (abs err of the product < ~3e-6)
__device__ __forceinline__ float sig_fast(float x) {
    return __fdividef(1.0f, 1.0f + __expf(-x));
}

__device__ __forceinline__ unsigned int ordered_float(float f) {
    unsigned int u = __float_as_uint(f);
    return (u & 0x80000000u) ? ~u : (u | 0x80000000u);
}
__device__ __forceinline__ float inv_ordered(unsigned int u) {
    return __uint_as_float((u & 0x80000000u) ? (u ^ 0x80000000u) : ~u);
}
// monotone linear bin over (0.3, 1.0] (same function everywhere -> consistent)
__device__ __forceinline__ int bin_of(float s) {
    int q = (int)(__fmul_rn(__fsub_rn(s, 0.3f), 1462.857f));
    if (q < 0) q = 0;
    return (q > NBIN - 1) ? (NBIN - 1) : q;
}

// anchor index -> level info
__device__ __forceinline__ void level_of(int idx, int& HW, int& W, float& stride, int& p, int& lvl) {
    if (idx < P3_END)      { HW = 25600; W = 160; stride = 8.f;  p = idx;          lvl = 0; }
    else if (idx < P4_END) { HW = 6400;  W = 80;  stride = 16.f; p = idx - P3_END; lvl = 1; }
    else                   { HW = 1600;  W = 40;  stride = 32.f; p = idx - P4_END; lvl = 2; }
}

// ------------------------------------------- decode (pure float approx) ----
// grid (33, 64): blockIdx.y = batch, 4 anchors per thread (float4 loads).
__global__ void decode_approx_kernel(const float* __restrict__ cls3,
                                     const float* __restrict__ obj3,
                                     const float* __restrict__ cls4,
                                     const float* __restrict__ obj4,
                                     const float* __restrict__ cls5,
                                     const float* __restrict__ obj5)
{
    int b = blockIdx.y;
    int q = blockIdx.x * 256 + threadIdx.x;
    if (q >= NA4) return;
    int a = q * 4;

    const float* cls; const float* obj; int HW, p;
    if (a < P3_END)      { cls = cls3; obj = obj3; HW = 25600; p = a; }
    else if (a < P4_END) { cls = cls4; obj = obj4; HW = 6400;  p = a - P3_END; }
    else                 { cls = cls5; obj = obj5; HW = 1600;  p = a - P4_END; }

    float4 o4  = *(const float4*)(obj + b * HW + p);
    float4 c04 = *(const float4*)(cls + (b * 2 + 0) * HW + p);
    float4 c14 = *(const float4*)(cls + (b * 2 + 1) * HW + p);

    float oo[4]  = {o4.x, o4.y, o4.z, o4.w};
    float cc0[4] = {c04.x, c04.y, c04.z, c04.w};
    float cc1[4] = {c14.x, c14.y, c14.z, c14.w};

    float ap[4]; bool ps[4]; int cnt = 0;
    #pragma unroll
    for (int j = 0; j < 4; ++j) {
        float cm = fmaxf(cc0[j], cc1[j]);
        float v  = sig_fast(oo[j]) * sig_fast(cm);
        ap[j] = v;
        ps[j] = (v >= 0.29999f);     // 0.3 - 1e-5 safety margin over approx error
        cnt  += ps[j] ? 1 : 0;
    }
    if (cnt) {
        int pos = atomicAdd(&g_cnt[b], cnt);
        ull* dst = g_cand + b * NA;
        #pragma unroll
        for (int j = 0; j < 4; ++j) {
            if (ps[j]) {
                int ai = a + j;
                dst[pos++] = ((ull)ordered_float(ap[j]) << 32) |
                             (unsigned int)(~(unsigned int)ai);
                atomicAdd(&g_hist[b][bin_of(ap[j])], 1);
            }
        }
    }
}

// ------------------------------- fused select (exact top-k) + NMS ----------
__global__ void select_nms_kernel(const float* __restrict__ cls3,
                                  const float* __restrict__ reg3,
                                  const float* __restrict__ obj3,
                                  const float* __restrict__ cls4,
                                  const float* __restrict__ reg4,
                                  const float* __restrict__ obj4,
                                  const float* __restrict__ cls5,
                                  const float* __restrict__ reg5,
                                  const float* __restrict__ obj5,
                                  float* __restrict__ out)
{
    // shared memory union: select phase (16KB) vs NMS phase (42KB)
    __shared__ __align__(16) unsigned char smem_raw[43008];
    int*    hist = (int*)smem_raw;                    // [0, 4K)   select + radix
    int*    cidx = (int*)(smem_raw + 4096);           // [4K, 8K)  gathered anchor idx
    ull*    ckey = (ull*)(smem_raw + 8192);           // [8K, 16K) exact keys / sort
    float4* sbox = (float4*)smem_raw;                 // [0, 8K)   NMS phase
    float*  sar  = (float*)(smem_raw + 8192);         // [8K, 10K)
    unsigned int* adj = (unsigned int*)(smem_raw + 10240); // [10K, 42K) 512x16

    __shared__ int  coarse[NBIN / 4];
    __shared__ int  s_qp, s_cnt, s_nvalid, s_fallback;
    __shared__ ull  s_prefix;
    __shared__ int  s_k;
    __shared__ unsigned int s_validw[16];
    __shared__ unsigned char skeep[512];

    int b   = blockIdx.x;
    int tid = threadIdx.x;
    int cnt_all = g_cnt[b];

    const float* CLS[3] = {cls3, cls4, cls5};
    const float* REG[3] = {reg3, reg4, reg5};
    const float* OBJ[3] = {obj3, obj4, obj5};

    // ---- phase A: pivot bin from approx histogram ----
    for (int d = tid; d < NBIN; d += 512) hist[d] = g_hist[b][d];
    if (tid == 0) { s_cnt = 0; s_nvalid = 0; s_fallback = (cnt_all < TOPK) ? 1 : 0; }
    __syncthreads();

    if (!s_fallback) {
        if (tid < NBIN / 4)
            coarse[tid] = hist[4 * tid] + hist[4 * tid + 1] + hist[4 * tid + 2] + hist[4 * tid + 3];
        __syncthreads();
        if (tid == 0) {
            int cum = 0, qp = 0;
            for (int g = NBIN / 4 - 1; g >= 0; --g) {
                if (cum + coarse[g] >= TOPK) {
                    for (int d = 4 * g + 3; d >= 4 * g; --d) {
                        if (cum + hist[d] >= TOPK) { qp = d; break; }
                        cum += hist[d];
                    }
                    break;
                }
                cum += coarse[g];
            }
            s_qp = (qp > 0) ? qp - 1 : 0;   // 1-bin relaxation covers approx error
        }
        __syncthreads();

        // ---- phase B: gather candidate indices with bin >= qp-1 ----
        int qp = s_qp;
        const ull* cl = g_cand + b * NA;
        for (int i = tid; i < cnt_all; i += 512) {
            ull key = cl[i];
            float s = inv_ordered((unsigned int)(key >> 32));
            if (bin_of(s) >= qp) {
                int pos = atomicAdd(&s_cnt, 1);
                if (pos < CAND) cidx[pos] = (int)(~(unsigned int)key);
                else            s_fallback = 1;
            }
        }
        __syncthreads();

        // ---- phase C: exact scores for gathered candidates only ----
        if (!s_fallback) {
            int m = s_cnt;
            for (int it = tid; it < m; it += 512) {
                int idx = cidx[it];
                int HW, W, p, lvl; float stride;
                level_of(idx, HW, W, stride, p, lvl);
                const float* cls = CLS[lvl];
                const float* obj = OBJ[lvl];
                float o  = obj[b * HW + p];
                float c0 = cls[(b * 2 + 0) * HW + p];
                float c1 = cls[(b * 2 + 1) * HW + p];
                float cmax = fmaxf(c0, c1);
                float so   = sig_e(o);
                float scm  = sig_e(cmax);
                float smax = __fmul_rn(so, scm);     // == max(s0,s1), monotonicity
                ull key = 0ull;
                if (smax > SCORE_THRESH) {
                    key = ((ull)ordered_float(smax) << 32) |
                          (unsigned int)(~(unsigned int)idx);
                    atomicAdd(&s_nvalid, 1);
                }
                ckey[it] = key;
            }
            __syncthreads();
            if (tid == 0 && s_nvalid < TOPK) s_fallback = 1;
            __syncthreads();
        }
    }

    // ---- phase E: full exact fallback (generality; not taken on this data) --
    if (s_fallback) {
        float* sc = g_scores + b * NA;
        for (int i = tid; i < NA; i += 512) {
            int HW, W, p, lvl; float stride;
            level_of(i, HW, W, stride, p, lvl);
            const float* cls = CLS[lvl];
            const float* obj = OBJ[lvl];
            float o  = obj[b * HW + p];
            float c0 = cls[(b * 2 + 0) * HW + p];
            float c1 = cls[(b * 2 + 1) * HW + p];
            float smax = __fmul_rn(sig_e(o), sig_e(fmaxf(c0, c1)));
            sc[i] = (smax > SCORE_THRESH) ? smax : -1.0f;
        }
        if (tid == 0) { s_prefix = 0ull; s_k = TOPK; s_cnt = 0; }
        __syncthreads();
        for (int pp = 7; pp >= 0; --pp) {
            for (int d = tid; d < 256; d += 512) hist[d] = 0;
            __syncthreads();
            ull pref = s_prefix;
            int sh = (pp + 1) * 8;
            for (int i = tid; i < NA; i += 512) {
                ull key = ((ull)ordered_float(sc[i]) << 32) |
                          (unsigned int)(~(unsigned int)i);
                bool match = (pp == 7) || ((key >> sh) == (pref >> sh));
                if (match) atomicAdd(&hist[(unsigned int)(key >> (pp * 8)) & 0xFFu], 1);
            }
            __syncthreads();
            if (tid == 0) {
                int k = s_k;
                for (int d = 255; d >= 0; --d) {
                    int c = hist[d];
                    if (k <= c) { s_prefix = pref | ((ull)d << (pp * 8)); break; }
                    k -= c;
                }
                s_k = k;
            }
            __syncthreads();
        }
        ull pivot = s_prefix;
        for (int i = tid; i < NA; i += 512) {
            ull key = ((ull)ordered_float(sc[i]) << 32) |
                      (unsigned int)(~(unsigned int)i);
            if (key >= pivot) {
                int pos = atomicAdd(&s_cnt, 1);
                if (pos < CAND) ckey[pos] = key;
            }
        }
        __syncthreads();
    }

    // ---- phase D: pad + bitonic sort (descending), 1024 / 512 threads ----
    int cnt = s_cnt; if (cnt > CAND) cnt = CAND;
    for (int s = tid; s < CAND; s += 512)
        if (s >= cnt) ckey[s] = 0ull;
    __syncthreads();

    for (int k = 2; k <= CAND; k <<= 1) {
        for (int j = k >> 1; j > 0; j >>= 1) {
            #pragma unroll
            for (int qq = 0; qq < 2; ++qq) {
                int i = tid + qq * 512;
                int ixj = i ^ j;
                if (ixj > i) {
                    bool desc = ((i & k) == 0);
                    ull ka = ckey[i], kb = ckey[ixj];
                    if (desc ? (ka < kb) : (ka > kb)) { ckey[i] = kb; ckey[ixj] = ka; }
                }
            }
            __syncthreads();
        }
    }

    // ---- transition: grab my key, then repurpose shared for NMS ----
    ull myk = ckey[tid];
    __syncthreads();

    // ---- phase F: NMS (box + label decode for top-500 only) ----
    int r = tid;
    float4 bb = make_float4(0.f, 0.f, 0.f, 0.f);
    float  sc = -1.0f;
    int    lab = 0;
    bool   validf = false;

    if (r < TOPK) {
        int idx = (int)(~(unsigned int)myk);
        sc = inv_ordered((unsigned int)(myk >> 32));
        if ((unsigned int)idx >= (unsigned int)NA) idx = 0;   // defensive (padded key)

        int HW, W, p, lvl; float stride;
        level_of(idx, HW, W, stride, p, lvl);
        const float* reg = REG[lvl];
        const float* cls = CLS[lvl];
        const float* obj = OBJ[lvl];
        int y = p / W;
        int x = p - y * W;

        // box decode (verified rounding sequence)
        float dx = reg[(b * 4 + 0) * HW + p];
        float dy = reg[(b * 4 + 1) * HW + p];
        float dw = reg[(b * 4 + 2) * HW + p];
        float dh = reg[(b * 4 + 3) * HW + p];
        float cx = __fmul_rn(__fadd_rn((float)x, sig_e(dx)), stride);
        float cy = __fmul_rn(__fadd_rn((float)y, sig_e(dy)), stride);
        float w  = __fmul_rn(exp_cr(dw), stride);
        float h  = __fmul_rn(exp_cr(dh), stride);
        float wh = __fdiv_rn(w, 2.0f);
        float hh = __fdiv_rn(h, 2.0f);
        bb.x = __fsub_rn(cx, wh);
        bb.y = __fsub_rn(cy, hh);
        bb.z = __fadd_rn(cx, wh);
        bb.w = __fadd_rn(cy, hh);

        // label (exact-band check)
        float c0 = cls[(b * 2 + 0) * HW + p];
        float c1 = cls[(b * 2 + 1) * HW + p];
        if (c1 > c0) {
            if (__fsub_rn(c1, c0) < 1e-3f) {
                float o   = obj[b * HW + p];
                float so2 = sig_e(o);
                float s0  = __fmul_rn(so2, sig_e(c0));
                float s1  = __fmul_rn(so2, sig_e(c1));
                lab = (s1 > s0) ? 1 : 0;
            } else {
                lab = 1;
            }
        }

        float off = __fmul_rn((float)lab, CLASS_OFFSET);
        float x1 = __fadd_rn(bb.x, off);
        float y1 = __fadd_rn(bb.y, off);
        float x2 = __fadd_rn(bb.z, off);
        float y2 = __fadd_rn(bb.w, off);
        sbox[r] = make_float4(x1, y1, x2, y2);
        sar[r]  = __fmul_rn(__fsub_rn(x2, x1), __fsub_rn(y2, y1));
        validf  = (sc > SCORE_THRESH);
    } else {
        sbox[r] = make_float4(0.f, 0.f, 0.f, 0.f);
        sar[r]  = 0.f;
    }

    unsigned vb = __ballot_sync(0xFFFFFFFFu, validf);
    if ((r & 31) == 0) s_validw[r >> 5] = vb;

    #pragma unroll
    for (int w = 0; w < 16; ++w) adj[r * 16 + w] = 0u;
    __syncthreads();

    // balanced half-pair enumeration (each unordered pair once)
    {
        float4 mb = sbox[r];
        float  ar = sar[r];
        int kmax = (r < 256) ? 256 : 255;
        for (int k = 1; k <= kmax; ++k) {
            int j = (r + k) & 511;
            float4 bj = sbox[j];
            float  aj = sar[j];
            float ix1 = fmaxf(mb.x, bj.x);
            float iy1 = fmaxf(mb.y, bj.y);
            float ix2 = fminf(mb.z, bj.z);
            float iy2 = fminf(mb.w, bj.w);
            float iw  = fmaxf(__fsub_rn(ix2, ix1), 0.f);
            float ih  = fmaxf(__fsub_rn(iy2, iy1), 0.f);
            float inter = __fmul_rn(iw, ih);
            float uniP  = __fadd_rn(__fsub_rn(__fadd_rn(ar, aj), inter), 1e-7f);
            float t    = __fmul_rn(0.5f, uniP);
            float diff = __fsub_rn(inter, t);
            bool hit;
            if (fabsf(diff) <= __fmul_rn(1e-6f, t)) {
                float iou = __fdiv_rn(inter, uniP);   // exact decision in guard band
                hit = (iou >= NMS_THRESH);
            } else {
                hit = (diff > 0.f);
            }
            if (hit) {
                atomicOr(&adj[r * 16 + (j >> 5)], 1u << (j & 31));
                atomicOr(&adj[j * 16 + (r >> 5)], 1u << (r & 31));
            }
        }
    }
    __syncthreads();

    // serial greedy on warp 0 with one-ahead adjacency prefetch
    if (r < 32) {
        int lane = r;
        unsigned avail   = (lane < 16) ? s_validw[lane]   : 0u;
        unsigned nextadj = (lane < 16) ? adj[0 * 16 + lane] : 0u;
        for (int i = 0; i < TOPK; ++i) {
            unsigned myadj = nextadj;
            nextadj = (lane < 16 && i + 1 < 512) ? adj[(i + 1) * 16 + lane] : 0u;
            unsigned aw = __shfl_sync(0xFFFFFFFFu, avail, i >> 5);
            bool keep_i = (aw >> (i & 31)) & 1u;
            if (lane == 0) skeep[i] = keep_i ? 1 : 0;
            if (keep_i) avail &= ~myadj;
        }
    }
    __syncthreads();

    // outputs: [boxes (B*500*4)] [scores] [labels] [keep]
    if (r < TOPK) {
        bool kp = skeep[r] != 0;
        int row = b * TOPK + r;
        float* ob = out + row * 4;
        ob[0] = kp ? bb.x : 0.f;
        ob[1] = kp ? bb.y : 0.f;
        ob[2] = kp ? bb.z : 0.f;
        ob[3] = kp ? bb.w : 0.f;
        const int SBASE = B * TOPK * 4;
        const int LBASE = SBASE + B * TOPK;
        const int KBASE = LBASE + B * TOPK;
        out[SBASE + row] = kp ? sc : 0.f;
        out[LBASE + row] = (float)lab;
        out[KBASE + row] = kp ? 1.f : 0.f;
    }
}

// --------------------------------------------------------------- launch ----
extern "C" void kernel_launch(void* const* d_in, const int* in_sizes, int n_in,
                              void* d_out, int out_size)
{
    const float* cls_p3 = (const float*)d_in[0];
    const float* reg_p3 = (const float*)d_in[1];
    const float* obj_p3 = (const float*)d_in[2];
    const float* cls_p4 = (const float*)d_in[3];
    const float* reg_p4 = (const float*)d_in[4];
    const float* obj_p4 = (const float*)d_in[5];
    const float* cls_p5 = (const float*)d_in[6];
    const float* reg_p5 = (const float*)d_in[7];
    const float* obj_p5 = (const float*)d_in[8];
    float* out = (float*)d_out;

    void* p_cnt = nullptr;  void* p_hist = nullptr;
    cudaGetSymbolAddress(&p_cnt,  g_cnt);
    cudaGetSymbolAddress(&p_hist, g_hist);
    cudaMemsetAsync(p_cnt,  0, B * sizeof(int), 0);
    cudaMemsetAsync(p_hist, 0, B * NBIN * sizeof(int), 0);

    dim3 dgrid(33, B);
    decode_approx_kernel<<<dgrid, 256>>>(cls_p3, obj_p3, cls_p4, obj_p4, cls_p5, obj_p5);
    select_nms_kernel<<<B, 512>>>(cls_p3, reg_p3, obj_p3,
                                  cls_p4, reg_p4, obj_p4,
                                  cls_p5, reg_p5, obj_p5, out);
}